// round 10
// baseline (speedup 1.0000x reference)
#include <cuda_runtime.h>
#include <cstdint>

namespace {
constexpr int L        = 512;
constexpr int C        = 128;
constexpr int F        = 128;
constexpr int Kw       = 7;
constexpr int L_OUT    = L - Kw + 1;   // 506
constexpr int KC       = Kw * C;       // 896
constexpr int BK       = 64;           // K chunk
constexpr int STAGES   = 3;
constexpr int NCHUNK   = KC / BK;      // 14
constexpr int A_STRIDE = BK + 4;       // 68 floats  (272B, 16B-mult) conflict-free
constexpr int B_STRIDE = F + 8;        // 136 floats (544B, 16B-mult) conflict-free
constexpr int A_STAGE_ELE = 128 * A_STRIDE;  // 8704
constexpr int B_STAGE_ELE = BK * B_STRIDE;   // 8704
constexpr size_t SMEM_BYTES = (size_t)STAGES * (A_STAGE_ELE + B_STAGE_ELE) * 4; // 208896
constexpr int NTHREADS = 256;          // 8 warps: 4 along M x 2 along N
constexpr uint32_t CHUNK_TX = 65536;   // A 32KB + B 32KB per stage
}

__device__ __forceinline__ uint32_t f2tf(float f) {
    uint32_t r;
    asm("cvt.rna.tf32.f32 %0, %1;" : "=r"(r) : "f"(f));
    return r;
}

__device__ __forceinline__ void mma_tf32(float* c, const uint32_t* a, const uint32_t* b) {
    asm volatile(
        "mma.sync.aligned.m16n8k8.row.col.f32.tf32.tf32.f32 "
        "{%0,%1,%2,%3},{%4,%5,%6,%7},{%8,%9},{%0,%1,%2,%3};"
        : "+f"(c[0]), "+f"(c[1]), "+f"(c[2]), "+f"(c[3])
        : "r"(a[0]), "r"(a[1]), "r"(a[2]), "r"(a[3]), "r"(b[0]), "r"(b[1]));
}

__device__ __forceinline__ void bulk_g2s(uint32_t dst, const void* src, uint32_t bytes,
                                         uint32_t mbar) {
    asm volatile(
        "cp.async.bulk.shared::cta.global.mbarrier::complete_tx::bytes [%0], [%1], %2, [%3];"
        :: "r"(dst), "l"(src), "r"(bytes), "r"(mbar) : "memory");
}

__device__ __forceinline__ void wait_parity(uint32_t mbar, uint32_t ph) {
    asm volatile(
        "{\n\t.reg .pred P;\n\t"
        "W_%=:\n\t"
        "mbarrier.try_wait.parity.acquire.cta.shared::cta.b64 P, [%0], %1;\n\t"
        "@!P bra W_%=;\n\t}"
        :: "r"(mbar), "r"(ph) : "memory");
}

__global__ void __launch_bounds__(NTHREADS, 1)
LocalBlock_kernel(const float* __restrict__ x, const float* __restrict__ w,
                  const float* __restrict__ bias, const float* __restrict__ gamma,
                  const float* __restrict__ beta, const float* __restrict__ mean,
                  const float* __restrict__ var, float* __restrict__ out)
{
    extern __shared__ float smem[];
    float* As = smem;                                 // [STAGES][128][A_STRIDE]
    float* Bs = smem + STAGES * A_STAGE_ELE;          // [STAGES][BK][B_STRIDE]
    __shared__ float s_inv[F];
    __shared__ float s_cst[F];
    __shared__ __align__(8) uint64_t s_mbar[STAGES];

    const int l    = blockIdx.x;
    const int tid  = threadIdx.x;
    const int warp = tid >> 5, lane = tid & 31;

    const float* xb = x + (size_t)l * C;              // A[b][k] = xb[b*L*C + k]
    const float* wb = w + (size_t)l * KC * F;         // B[k][f]

    const uint32_t sA   = (uint32_t)__cvta_generic_to_shared(As);
    const uint32_t sB   = (uint32_t)__cvta_generic_to_shared(Bs);
    const uint32_t mbar0 = (uint32_t)__cvta_generic_to_shared(s_mbar);

    if (tid < STAGES)
        asm volatile("mbarrier.init.shared::cta.b64 [%0], 1;"
                     :: "r"(mbar0 + tid * 8) : "memory");

    if (tid < F) {
        float iv = gamma[tid] * rsqrtf(var[tid] + 1e-3f);
        s_inv[tid] = iv;
        s_cst[tid] = bias[(size_t)l * F + tid] * iv + beta[tid] - mean[tid] * iv;
    }
    __syncthreads();   // mbarriers initialized before any bulk targets them

    // warp 0 drives all async loads: 128 A-row copies (256B) + 64 B-row copies (512B)
    auto load_stage = [&](int st, int kt) {
        const uint32_t mb = mbar0 + st * 8;
        if (lane == 0)
            asm volatile("mbarrier.arrive.expect_tx.shared::cta.b64 _, [%0], %1;"
                         :: "r"(mb), "r"(CHUNK_TX) : "memory");
        const uint32_t sa = sA + st * A_STAGE_ELE * 4;
        const uint32_t sb = sB + st * B_STAGE_ELE * 4;
        const int kc0 = kt * BK;
        #pragma unroll
        for (int i = 0; i < 4; i++) {
            int row = lane + i * 32;
            bulk_g2s(sa + row * (A_STRIDE * 4),
                     xb + (size_t)row * (L * C) + kc0, BK * 4, mb);
        }
        #pragma unroll
        for (int i = 0; i < 2; i++) {
            int row = lane + i * 32;
            bulk_g2s(sb + row * (B_STRIDE * 4),
                     wb + (size_t)(kc0 + row) * F, F * 4, mb);
        }
    };

    if (warp == 0) {
        load_stage(0, 0);
        load_stage(1, 1);
    }

    const int wm = (warp >> 1) * 32;   // 4 warps along M (batch)
    const int wn = (warp & 1) * 64;    // 2 warps along N (features)
    const int g4 = lane >> 2, t4 = lane & 3;

    float acc[2][8][4];
    #pragma unroll
    for (int mi = 0; mi < 2; mi++)
        #pragma unroll
        for (int ni = 0; ni < 8; ni++)
            #pragma unroll
            for (int q = 0; q < 4; q++) acc[mi][ni][q] = 0.f;

    for (int kt = 0; kt < NCHUNK; kt++) {
        __syncthreads();               // all warps done with chunk kt-1 -> its stage is free
        if (warp == 0 && kt + 2 < NCHUNK)
            load_stage((kt + 2) % STAGES, kt + 2);

        wait_parity(mbar0 + (kt % STAGES) * 8, (uint32_t)((kt / STAGES) & 1));

        const float* As_s = As + (kt % STAGES) * A_STAGE_ELE;
        const float* Bs_s = Bs + (kt % STAGES) * B_STAGE_ELE;

        #pragma unroll
        for (int k8 = 0; k8 < 8; k8++) {
            const int kb = k8 * 8;
            uint32_t a[2][4], b[8][2];
            #pragma unroll
            for (int mi = 0; mi < 2; mi++) {
                const float* ap = As_s + (wm + mi * 16 + g4) * A_STRIDE + kb + t4;
                a[mi][0] = f2tf(ap[0]);
                a[mi][1] = f2tf(ap[8 * A_STRIDE]);
                a[mi][2] = f2tf(ap[4]);
                a[mi][3] = f2tf(ap[8 * A_STRIDE + 4]);
            }
            #pragma unroll
            for (int ni = 0; ni < 8; ni++) {
                const float* bp = Bs_s + (kb + t4) * B_STRIDE + wn + ni * 8 + g4;
                b[ni][0] = f2tf(bp[0]);
                b[ni][1] = f2tf(bp[4 * B_STRIDE]);
            }
            #pragma unroll
            for (int mi = 0; mi < 2; mi++)
                #pragma unroll
                for (int ni = 0; ni < 8; ni++)
                    mma_tf32(acc[mi][ni], a[mi], b[ni]);
        }
    }

    // Epilogue: BN affine + ReLU, write out[b][l][f]
    #pragma unroll
    for (int mi = 0; mi < 2; mi++) {
        const int r0 = wm + mi * 16 + g4;   // batch index
        #pragma unroll
        for (int ni = 0; ni < 8; ni++) {
            const int col = wn + ni * 8 + t4 * 2;
            const float i0 = s_inv[col], i1 = s_inv[col + 1];
            const float k0 = s_cst[col], k1 = s_cst[col + 1];
            float v0 = fmaxf(fmaf(acc[mi][ni][0], i0, k0), 0.f);
            float v1 = fmaxf(fmaf(acc[mi][ni][1], i1, k1), 0.f);
            float v2 = fmaxf(fmaf(acc[mi][ni][2], i0, k0), 0.f);
            float v3 = fmaxf(fmaf(acc[mi][ni][3], i1, k1), 0.f);
            float2* o0 = (float2*)(out + (size_t)r0 * (L_OUT * F) + (size_t)l * F + col);
            float2* o1 = (float2*)(out + (size_t)(r0 + 8) * (L_OUT * F) + (size_t)l * F + col);
            *o0 = make_float2(v0, v1);
            *o1 = make_float2(v2, v3);
        }
    }
}

extern "C" void kernel_launch(void* const* d_in, const int* in_sizes, int n_in,
                              void* d_out, int out_size)
{
    (void)in_sizes; (void)n_in; (void)out_size;
    const float* x     = (const float*)d_in[0];
    const float* w     = (const float*)d_in[1];
    const float* bias  = (const float*)d_in[2];
    const float* gamma = (const float*)d_in[3];
    const float* beta  = (const float*)d_in[4];
    const float* mean  = (const float*)d_in[5];
    const float* var   = (const float*)d_in[6];
    float* out = (float*)d_out;

    cudaFuncSetAttribute(LocalBlock_kernel,
                         cudaFuncAttributeMaxDynamicSharedMemorySize,
                         (int)SMEM_BYTES);
    LocalBlock_kernel<<<L_OUT, NTHREADS, SMEM_BYTES>>>(x, w, bias, gamma, beta, mean, var, out);
}

// round 11
// speedup vs baseline: 3.0644x; 3.0644x over previous
#include <cuda_runtime.h>
#include <cstdint>

namespace {
constexpr int L        = 512;
constexpr int C        = 128;
constexpr int F        = 128;
constexpr int Kw       = 7;
constexpr int L_OUT    = L - Kw + 1;   // 506
constexpr int KC       = Kw * C;       // 896
constexpr int BK       = 64;           // K chunk
constexpr int BN       = 64;           // N half per CTA
constexpr int STAGES   = 2;
constexpr int NCHUNK   = KC / BK;      // 14
constexpr int A_STRIDE = BK + 4;       // 68 floats -> conflict-free A frag loads
constexpr int B_STRIDE = BN + 8;       // 72 floats -> conflict-free B frag loads
constexpr int A_STAGE_ELE = 128 * A_STRIDE;  // 8704
constexpr int B_STAGE_ELE = BK * B_STRIDE;   // 4608
constexpr size_t SMEM_BYTES = (size_t)STAGES * (A_STAGE_ELE + B_STAGE_ELE) * 4; // 106496
constexpr int NTHREADS = 128;          // 4 warps, all along M; each warp 32Mx64N
}

__device__ __forceinline__ uint32_t f2tf(float f) {
    uint32_t r;
    asm("cvt.rna.tf32.f32 %0, %1;" : "=r"(r) : "f"(f));
    return r;
}

__device__ __forceinline__ void mma_tf32(float* c, const uint32_t* a, const uint32_t* b) {
    asm volatile(
        "mma.sync.aligned.m16n8k8.row.col.f32.tf32.tf32.f32 "
        "{%0,%1,%2,%3},{%4,%5,%6,%7},{%8,%9},{%0,%1,%2,%3};"
        : "+f"(c[0]), "+f"(c[1]), "+f"(c[2]), "+f"(c[3])
        : "r"(a[0]), "r"(a[1]), "r"(a[2]), "r"(a[3]), "r"(b[0]), "r"(b[1]));
}

__global__ void __launch_bounds__(NTHREADS, 2)
LocalBlock_kernel(const float* __restrict__ x, const float* __restrict__ w,
                  const float* __restrict__ bias, const float* __restrict__ gamma,
                  const float* __restrict__ beta, const float* __restrict__ mean,
                  const float* __restrict__ var, float* __restrict__ out)
{
    extern __shared__ float smem[];
    float* As = smem;                                 // [STAGES][128][A_STRIDE]
    float* Bs = smem + STAGES * A_STAGE_ELE;          // [STAGES][BK][B_STRIDE]
    __shared__ float s_inv[BN];
    __shared__ float s_cst[BN];

    const int l    = blockIdx.x;
    const int nb   = blockIdx.y * BN;                 // N-half base (0 or 64)
    const int tid  = threadIdx.x;

    // Epilogue constants for this CTA's 64 feature columns
    if (tid < BN) {
        int g = nb + tid;
        float iv = gamma[g] * rsqrtf(var[g] + 1e-3f);
        s_inv[tid] = iv;
        s_cst[tid] = bias[(size_t)l * F + g] * iv + beta[g] - mean[g] * iv;
    }

    // A[b][kc] = x[b*L*C + l*C + kc]  (contiguous 896-run per batch row)
    const float* xb = x + (size_t)l * C;
    // B[kc][f_local] = w[l*KC*F + kc*F + nb + f_local]
    const float* wb = w + (size_t)l * KC * F + nb;

    const uint32_t sA = (uint32_t)__cvta_generic_to_shared(As);
    const uint32_t sB = (uint32_t)__cvta_generic_to_shared(Bs);

    auto load_stage = [&](int stage, int kc0) {
        const uint32_t sa = sA + stage * A_STAGE_ELE * 4;
        const uint32_t sb = sB + stage * B_STAGE_ELE * 4;
        // A chunk: 128 rows x 64 floats = 2048 float4 -> 16 per thread
        #pragma unroll
        for (int i = 0; i < 16; i++) {
            int idx = tid + i * NTHREADS;
            int row = idx >> 4;
            int c4  = (idx & 15) << 2;
            const float* g = xb + (size_t)row * (L * C) + kc0 + c4;
            asm volatile("cp.async.cg.shared.global [%0], [%1], 16;"
                         :: "r"(sa + (row * A_STRIDE + c4) * 4), "l"(g));
        }
        // B chunk: 64 rows x 64 floats = 1024 float4 -> 8 per thread
        #pragma unroll
        for (int i = 0; i < 8; i++) {
            int idx = tid + i * NTHREADS;
            int row = idx >> 4;
            int c4  = (idx & 15) << 2;
            const float* g = wb + (size_t)(kc0 + row) * F + c4;
            asm volatile("cp.async.cg.shared.global [%0], [%1], 16;"
                         :: "r"(sb + (row * B_STRIDE + c4) * 4), "l"(g));
        }
        asm volatile("cp.async.commit_group;");
    };

    // Prologue: stage 0 <- chunk 0
    load_stage(0, 0);

    const int warp = tid >> 5, lane = tid & 31;
    const int wm = warp * 32;          // 4 warps along M (batch)
    const int g4 = lane >> 2, t4 = lane & 3;

    float acc[2][8][4];
    #pragma unroll
    for (int mi = 0; mi < 2; mi++)
        #pragma unroll
        for (int ni = 0; ni < 8; ni++)
            #pragma unroll
            for (int q = 0; q < 4; q++) acc[mi][ni][q] = 0.f;

    for (int kt = 0; kt < NCHUNK; kt++) {
        // Prefetch next chunk into the other stage (freed by barrier at end of
        // previous iteration). Always commit so wait_group 1 gates chunk kt.
        if (kt + 1 < NCHUNK)
            load_stage((kt + 1) & 1, (kt + 1) * BK);
        else
            asm volatile("cp.async.commit_group;");

        asm volatile("cp.async.wait_group 1;");
        __syncthreads();               // chunk kt resident & published

        const float* As_s = As + (kt & 1) * A_STAGE_ELE;
        const float* Bs_s = Bs + (kt & 1) * B_STAGE_ELE;

        #pragma unroll
        for (int k8 = 0; k8 < 8; k8++) {
            const int kb = k8 * 8;
            uint32_t a[2][4], b[8][2];
            #pragma unroll
            for (int mi = 0; mi < 2; mi++) {
                const float* ap = As_s + (wm + mi * 16 + g4) * A_STRIDE + kb + t4;
                a[mi][0] = f2tf(ap[0]);
                a[mi][1] = f2tf(ap[8 * A_STRIDE]);
                a[mi][2] = f2tf(ap[4]);
                a[mi][3] = f2tf(ap[8 * A_STRIDE + 4]);
            }
            #pragma unroll
            for (int ni = 0; ni < 8; ni++) {
                const float* bp = Bs_s + (kb + t4) * B_STRIDE + ni * 8 + g4;
                b[ni][0] = f2tf(bp[0]);
                b[ni][1] = f2tf(bp[4 * B_STRIDE]);
            }
            #pragma unroll
            for (int mi = 0; mi < 2; mi++)
                #pragma unroll
                for (int ni = 0; ni < 8; ni++)
                    mma_tf32(acc[mi][ni], a[mi], b[ni]);
        }
        __syncthreads();               // all warps done with stage kt before overwrite
    }

    // Epilogue: BN affine + ReLU, write out[b][l][nb+col]
    #pragma unroll
    for (int mi = 0; mi < 2; mi++) {
        const int r0 = wm + mi * 16 + g4;   // batch index
        #pragma unroll
        for (int ni = 0; ni < 8; ni++) {
            const int col = ni * 8 + t4 * 2;     // local feature col
            const float i0 = s_inv[col], i1 = s_inv[col + 1];
            const float k0 = s_cst[col], k1 = s_cst[col + 1];
            float v0 = fmaxf(fmaf(acc[mi][ni][0], i0, k0), 0.f);
            float v1 = fmaxf(fmaf(acc[mi][ni][1], i1, k1), 0.f);
            float v2 = fmaxf(fmaf(acc[mi][ni][2], i0, k0), 0.f);
            float v3 = fmaxf(fmaf(acc[mi][ni][3], i1, k1), 0.f);
            float2* o0 = (float2*)(out + (size_t)r0 * (L_OUT * F) + (size_t)l * F + nb + col);
            float2* o1 = (float2*)(out + (size_t)(r0 + 8) * (L_OUT * F) + (size_t)l * F + nb + col);
            *o0 = make_float2(v0, v1);
            *o1 = make_float2(v2, v3);
        }
    }
}

extern "C" void kernel_launch(void* const* d_in, const int* in_sizes, int n_in,
                              void* d_out, int out_size)
{
    (void)in_sizes; (void)n_in; (void)out_size;
    const float* x     = (const float*)d_in[0];
    const float* w     = (const float*)d_in[1];
    const float* bias  = (const float*)d_in[2];
    const float* gamma = (const float*)d_in[3];
    const float* beta  = (const float*)d_in[4];
    const float* mean  = (const float*)d_in[5];
    const float* var   = (const float*)d_in[6];
    float* out = (float*)d_out;

    cudaFuncSetAttribute(LocalBlock_kernel,
                         cudaFuncAttributeMaxDynamicSharedMemorySize,
                         (int)SMEM_BYTES);
    dim3 grid(L_OUT, 2);
    LocalBlock_kernel<<<grid, NTHREADS, SMEM_BYTES>>>(x, w, bias, gamma, beta, mean, var, out);
}